// round 2
// baseline (speedup 1.0000x reference)
#include <cuda_runtime.h>
#include <cstdint>

// Problem constants (fixed per dataset)
#define N_NODES     100000
#define D_FEAT      128
#define N_EDGES_MAX 50008

// Scratch: segment start offsets (d_seg_start[e] = first flat index with seg id >= e)
__device__ int d_seg_start[N_EDGES_MAX + 1];

// ---------------------------------------------------------------------------
// Kernel 1: binary-search run boundaries of the sorted segment_ids (int32).
// One thread per edge id e in [0, n_edges]; finds lower_bound(seg_ids, e).
// ---------------------------------------------------------------------------
__global__ void compute_offsets_kernel(const int* __restrict__ seg_ids,
                                       int flat, int n_edges) {
    int e = blockIdx.x * blockDim.x + threadIdx.x;
    if (e > n_edges) return;
    int lo = 0, hi = flat;
    while (lo < hi) {
        int mid = (lo + hi) >> 1;
        if (__ldg(&seg_ids[mid]) < e) lo = mid + 1; else hi = mid;
    }
    d_seg_start[e] = lo;
}

// ---------------------------------------------------------------------------
// Kernel 2: warp-per-segment ragged segment-max.
// Each lane owns 4 of the 128 features (one float4). Node indices (int32) for
// the segment are loaded coalesced 32-at-a-time and broadcast with shfl, so
// the loop body's only memory op is the perfectly coalesced 512B row load.
// ---------------------------------------------------------------------------
__global__ void seg_max_kernel(const float4* __restrict__ emb,      // [N_NODES * 32] float4
                               const int* __restrict__ node_idx,
                               float4* __restrict__ out,            // [n_edges * 32] float4
                               int n_edges) {
    int gwarp = (blockIdx.x * blockDim.x + threadIdx.x) >> 5;
    int lane  = threadIdx.x & 31;
    if (gwarp >= n_edges) return;

    int start = d_seg_start[gwarp];
    int end   = d_seg_start[gwarp + 1];

    float4 acc = make_float4(0.f, 0.f, 0.f, 0.f);  // empty segment -> zeros

    if (start < end) {
        const float NEG = -3.402823466e+38f;
        acc = make_float4(NEG, NEG, NEG, NEG);

        for (int base = start; base < end; base += 32) {
            int cnt = end - base;
            if (cnt > 32) cnt = 32;
            // coalesced index prefetch: each lane loads one upcoming index
            int nd_l = 0;
            if (lane < cnt) nd_l = __ldg(&node_idx[base + lane]);

            #pragma unroll 4
            for (int j = 0; j < cnt; j++) {
                int nd = __shfl_sync(0xffffffffu, nd_l, j);
                float4 v = __ldg(&emb[(size_t)nd * 32 + lane]);
                acc.x = fmaxf(acc.x, v.x);
                acc.y = fmaxf(acc.y, v.y);
                acc.z = fmaxf(acc.z, v.z);
                acc.w = fmaxf(acc.w, v.w);
            }
        }
    }

    out[(size_t)gwarp * 32 + lane] = acc;
}

// ---------------------------------------------------------------------------
// Launch
// inputs (metadata order): emb_table f32 [100000,128], node_idx i32 [1.6M],
//                          segment_ids i32 [1.6M], num_segments scalar
// output: f32 [50000,128]
// ---------------------------------------------------------------------------
extern "C" void kernel_launch(void* const* d_in, const int* in_sizes, int n_in,
                              void* d_out, int out_size) {
    const float4* emb      = (const float4*)d_in[0];
    const int*    node_idx = (const int*)d_in[1];
    const int*    seg_ids  = (const int*)d_in[2];
    float4*       out      = (float4*)d_out;

    int flat    = in_sizes[1];            // 1,600,000
    int n_edges = out_size / D_FEAT;      // 50,000

    // Kernel 1: boundaries
    {
        int threads = 256;
        int blocks  = (n_edges + 1 + threads - 1) / threads;
        compute_offsets_kernel<<<blocks, threads>>>(seg_ids, flat, n_edges);
    }

    // Kernel 2: warp-per-segment max
    {
        int threads = 256;                         // 8 warps = 8 segments / block
        int blocks = (n_edges * 32 + threads - 1) / threads;
        seg_max_kernel<<<blocks, threads>>>(emb, node_idx, out, n_edges);
    }
}

// round 3
// speedup vs baseline: 1.0797x; 1.0797x over previous
#include <cuda_runtime.h>
#include <cstdint>

#define D_FEAT      128
#define N_EDGES_MAX 50008

// Scratch: segment start offsets (d_seg_start[e] = first flat index with seg id >= e)
__device__ int d_seg_start[N_EDGES_MAX + 1];

// ---------------------------------------------------------------------------
// Kernel 1: run-boundary detection on the sorted segment_ids (int32).
// Thread i compares seg[i] with seg[i-1]; for every id in the gap it owns the
// boundary write. 1.6M coalesced reads, 50K scattered writes  (~2us).
// ---------------------------------------------------------------------------
__global__ void offsets_kernel(const int* __restrict__ seg_ids,
                               int flat, int n_edges) {
    int i = blockIdx.x * blockDim.x + threadIdx.x;
    if (i >= flat) return;
    int cur  = __ldg(&seg_ids[i]);
    int prev = (i == 0) ? -1 : __ldg(&seg_ids[i - 1]);
    for (int e = prev + 1; e <= cur; e++)       // usually 0 or 1 iterations
        d_seg_start[e] = i;
    if (i == flat - 1) {
        for (int e = cur + 1; e <= n_edges; e++)
            d_seg_start[e] = flat;
    }
}

// ---------------------------------------------------------------------------
// Kernel 2: warp-per-segment ragged segment-max, 4-wide load batching.
// Each lane owns one float4 (4 of 128 feats). Indices are fetched coalesced
// 32-ahead and shfl-broadcast. Ragged tails are padded with the segment's
// FIRST node index — max is idempotent, so the redundant loads are free of
// correctness cost and keep 4 independent 512B row loads in flight.
// ---------------------------------------------------------------------------
__global__ void __launch_bounds__(256)
seg_max_kernel(const float4* __restrict__ emb,      // [N_NODES * 32] float4
               const int* __restrict__ node_idx,
               float4* __restrict__ out,            // [n_edges * 32] float4
               int n_edges) {
    int gwarp = (blockIdx.x * blockDim.x + threadIdx.x) >> 5;
    int lane  = threadIdx.x & 31;
    if (gwarp >= n_edges) return;

    int start = d_seg_start[gwarp];
    int end   = d_seg_start[gwarp + 1];

    if (start >= end) {                               // empty segment -> zeros
        out[(size_t)gwarp * 32 + lane] = make_float4(0.f, 0.f, 0.f, 0.f);
        return;
    }

    const float NEG = -3.402823466e+38f;
    float4 acc0 = make_float4(NEG, NEG, NEG, NEG);
    float4 acc1 = acc0;

    const float4* embl = emb + lane;
    int first = __ldg(&node_idx[start]);              // pad index (idempotent)

    for (int base = start; base < end; base += 32) {
        int cnt = end - base;
        if (cnt > 32) cnt = 32;
        int nd_l = (lane < cnt) ? __ldg(&node_idx[base + lane]) : first;
        int cnt4 = (cnt + 3) & ~3;                    // pad to multiple of 4

        for (int j = 0; j < cnt4; j += 4) {
            int n0 = __shfl_sync(0xffffffffu, nd_l, j);
            int n1 = __shfl_sync(0xffffffffu, nd_l, j + 1);
            int n2 = __shfl_sync(0xffffffffu, nd_l, j + 2);
            int n3 = __shfl_sync(0xffffffffu, nd_l, j + 3);
            // 4 independent coalesced 512B row loads in flight
            float4 v0 = __ldg(embl + (size_t)n0 * 32);
            float4 v1 = __ldg(embl + (size_t)n1 * 32);
            float4 v2 = __ldg(embl + (size_t)n2 * 32);
            float4 v3 = __ldg(embl + (size_t)n3 * 32);
            acc0.x = fmaxf(acc0.x, fmaxf(v0.x, v1.x));
            acc0.y = fmaxf(acc0.y, fmaxf(v0.y, v1.y));
            acc0.z = fmaxf(acc0.z, fmaxf(v0.z, v1.z));
            acc0.w = fmaxf(acc0.w, fmaxf(v0.w, v1.w));
            acc1.x = fmaxf(acc1.x, fmaxf(v2.x, v3.x));
            acc1.y = fmaxf(acc1.y, fmaxf(v2.y, v3.y));
            acc1.z = fmaxf(acc1.z, fmaxf(v2.z, v3.z));
            acc1.w = fmaxf(acc1.w, fmaxf(v2.w, v3.w));
        }
    }

    float4 r;
    r.x = fmaxf(acc0.x, acc1.x);
    r.y = fmaxf(acc0.y, acc1.y);
    r.z = fmaxf(acc0.z, acc1.z);
    r.w = fmaxf(acc0.w, acc1.w);
    out[(size_t)gwarp * 32 + lane] = r;
}

// ---------------------------------------------------------------------------
// Launch
// inputs: emb_table f32 [100000,128], node_idx i32 [1.6M],
//         segment_ids i32 [1.6M], num_segments scalar
// output: f32 [50000,128]
// ---------------------------------------------------------------------------
extern "C" void kernel_launch(void* const* d_in, const int* in_sizes, int n_in,
                              void* d_out, int out_size) {
    const float4* emb      = (const float4*)d_in[0];
    const int*    node_idx = (const int*)d_in[1];
    const int*    seg_ids  = (const int*)d_in[2];
    float4*       out      = (float4*)d_out;

    int flat    = in_sizes[1];            // 1,600,000
    int n_edges = out_size / D_FEAT;      // 50,000

    // Kernel 1: boundaries via run detection
    {
        int threads = 256;
        int blocks  = (flat + threads - 1) / threads;
        offsets_kernel<<<blocks, threads>>>(seg_ids, flat, n_edges);
    }

    // Kernel 2: warp-per-segment max
    {
        int threads = 256;                         // 8 warps = 8 segments / block
        int blocks  = (n_edges * 32 + threads - 1) / threads;
        seg_max_kernel<<<blocks, threads>>>(emb, node_idx, out, n_edges);
    }
}